// round 16
// baseline (speedup 1.0000x reference)
#include <cuda_runtime.h>
#include <cuda_fp16.h>
#include <cstdint>

// VectorQuantizer: out[m,:] = codebook[argmin_k (||c_k||^2 - 2 x_m . c_k)]
// M=65536 tokens, D=256, K=1024 codes, fp32.
//
// R16: R14 (fp16 3-term split, TMA pre-split operands — best main kernel) +
// R11's ping-pong TMEM accumulator banks (NCH=128, banks at cols 0/128).
// Under fp16 the chunk-epilogue serialization is ~33% of CTA time; banked
// accumulators hide it behind the other bank's MMA stream. Depth 3, occ 2.
// Fallback path (plain sm_103 PTX pass): proven SIMT tiled kernel.

#if defined(__CUDA_ARCH_FEAT_SM103_ALL) || defined(__CUDA_ARCH_FEAT_SM100_ALL) || \
    defined(__CUDA_ARCH_SPECIFIC__) || defined(__CUDA_ARCH_FAMILY_SPECIFIC__)
#define VQ_TC 1
#else
#define VQ_TC 0
#endif

#define D_DIM 256
#define K_CODES 1024
#define MT 128                      // tokens per CTA tile (MMA M)
#define NCH 128                     // codes per chunk (MMA N) -> ping-pong banks
#define KC 32                       // d-slice per stage (32 fp16 = 64B rows)
#define NCHUNKS (K_CODES / NCH)     // 8
#define KSTAGES (D_DIM / KC)        // 8 stages per chunk
#define NSTAGES_TOTAL (NCHUNKS * KSTAGES)  // 64
#define NSLOTS 3
#define NTILES 512                  // 65536 / MT
#define NTHREADS 320                // 8 epilogue warps + loader warp + MMA warp

// ---- SMEM layout (bytes from dynamic smem base) ----
#define SM_TMEMPTR 0
#define MB_FULL(s)  (8 + 8 * (s))     // 8,16,24
#define MB_EMPTY(s) (32 + 8 * (s))    // 32,40,48
#define MB_EPI(b)   (56 + 8 * (b))    // 56,64
#define MB_EPIDONE(b) (72 + 8 * (b))  // 72,80
#define SM_ASSIGN  128                // 128 * 4B
#define SM_REDD    1024               // [2][128] float
#define SM_REDI    2048               // [2][128] int
#define SM_C2      4096               // 1024 * 4B
#define SM_TILES   8192
// stage layout (SW64, 64B rows of 32 fp16): A hi 8K | A lo 8K | B hi 8K | B lo 8K
#define AS_HI 0
#define AS_LO 8192
#define BS_HI 16384
#define BS_LO 24576
#define STAGE_BYTES 32768
#define SMEM_TOTAL (SM_TILES + NSLOTS * STAGE_BYTES)   // 106496 -> 2 CTAs/SM

// idesc: c=F32(1<<4), a=FP16(0), b=FP16(0), N=128(16<<17), M=128(8<<24)
#define IDESC 0x8200010u

__device__ float g_c2[K_CODES];
// Pre-split fp16 operand tiles in SW64-swizzled SMEM byte layout (64B rows).
__device__ __align__(16) uint8_t g_apre[NTILES][KSTAGES][16384];   // hi 8K | lo 8K
__device__ __align__(16) uint8_t g_bpre[NCHUNKS][KSTAGES][16384];  // hi 8K | lo 8K

__device__ __forceinline__ uint32_t sw64(uint32_t off) { return off ^ ((off >> 3) & 0x30); }

// split a float4 into packed fp16 hi (uint2) and lo (uint2)
__device__ __forceinline__ void split4(float4 v, uint2& H, uint2& L) {
    __half hx = __float2half_rn(v.x), hy = __float2half_rn(v.y);
    __half hz = __float2half_rn(v.z), hw = __float2half_rn(v.w);
    __half lx = __float2half_rn(v.x - __half2float(hx));
    __half ly = __float2half_rn(v.y - __half2float(hy));
    __half lz = __float2half_rn(v.z - __half2float(hz));
    __half lw = __float2half_rn(v.w - __half2float(hw));
    H.x = (uint32_t)__half_as_ushort(hx) | ((uint32_t)__half_as_ushort(hy) << 16);
    H.y = (uint32_t)__half_as_ushort(hz) | ((uint32_t)__half_as_ushort(hw) << 16);
    L.x = (uint32_t)__half_as_ushort(lx) | ((uint32_t)__half_as_ushort(ly) << 16);
    L.y = (uint32_t)__half_as_ushort(lz) | ((uint32_t)__half_as_ushort(lw) << 16);
}

// Fused pre-pass: one launch.
//   [0, 4096)        A split  (tile = bid>>3, kc = bid&7)
//   [4096, 4160)     B split  (chunk = b>>3, kc = b&7)
//   [4160, 4164)     c2
#define APRE_BLOCKS (NTILES * KSTAGES)          // 4096
#define BPRE_BLOCKS (NCHUNKS * KSTAGES)         // 64
#define PRE_BLOCKS (APRE_BLOCKS + BPRE_BLOCKS + 4)

__global__ void pre_kernel(const float* __restrict__ x, const float* __restrict__ cb) {
    const int bid = blockIdx.x;
    const int tid = threadIdx.x;
    if (bid < APRE_BLOCKS) {
        const int tile = bid >> 3;
        const int kc = bid & 7;
        const int m0 = tile * MT;
        uint8_t* dst = g_apre[tile][kc];
#pragma unroll
        for (int t = 0; t < 4; t++) {
            int idx = tid + t * 256;            // 1024 float4 (128 rows x 8 f4/row)
            int row = idx >> 3, dv = idx & 7;
            float4 v = *(const float4*)(x + (size_t)(m0 + row) * D_DIM + kc * KC + dv * 4);
            uint2 H, L;
            split4(v, H, L);
            uint32_t off = sw64((uint32_t)row * 64 + dv * 8);
            *(uint2*)(dst + off) = H;
            *(uint2*)(dst + 8192 + off) = L;
        }
    } else if (bid < APRE_BLOCKS + BPRE_BLOCKS) {
        const int b = bid - APRE_BLOCKS;
        const int chunk = b >> 3;
        const int kc = b & 7;
        const int n0 = chunk * NCH;
        uint8_t* dst = g_bpre[chunk][kc];
#pragma unroll
        for (int t = 0; t < 4; t++) {
            int idx = tid + t * 256;            // 1024 float4 (128 rows x 8 f4/row)
            int row = idx >> 3, dv = idx & 7;
            float4 v = *(const float4*)(cb + (size_t)(n0 + row) * D_DIM + kc * KC + dv * 4);
            uint2 H, L;
            split4(v, H, L);
            uint32_t off = sw64((uint32_t)row * 64 + dv * 8);
            *(uint2*)(dst + off) = H;
            *(uint2*)(dst + 8192 + off) = L;
        }
    } else {
        const int k = (bid - APRE_BLOCKS - BPRE_BLOCKS) * 256 + tid;
        if (k < K_CODES) {
            const float4* p = (const float4*)(cb + (size_t)k * D_DIM);
            float s = 0.f;
#pragma unroll 8
            for (int i = 0; i < D_DIM / 4; i++) {
                float4 v = p[i];
                s += v.x * v.x + v.y * v.y + v.z * v.z + v.w * v.w;
            }
            g_c2[k] = s;
        }
    }
}

// ---------------- helpers ----------------
__device__ __forceinline__ uint32_t smem_u32(const void* p) {
    uint32_t a;
    asm("{ .reg .u64 t; cvta.to.shared.u64 t, %1; cvt.u32.u64 %0, t; }" : "=r"(a) : "l"(p));
    return a;
}

#if VQ_TC
__device__ __forceinline__ uint64_t make_desc_sw64(uint32_t addr) {
    // SW64 K-major: layout=4, version=1, SBO=32 (512B = 8 rows x 64B), LBO=1
    uint64_t d = ((uint64_t)4 << 61) | ((uint64_t)1 << 46) | ((uint64_t)32 << 32) | ((uint64_t)1 << 16);
    return d | (uint64_t)((addr >> 4) & 0x3FFF);
}
__device__ __forceinline__ void mma_f16(uint32_t d, uint64_t a, uint64_t b, uint32_t en) {
    asm volatile(
        "{\n\t.reg .pred p;\n\tsetp.ne.u32 p, %4, 0;\n\t"
        "tcgen05.mma.cta_group::1.kind::f16 [%0], %1, %2, %3, {%5, %5, %5, %5}, p;\n\t}"
        :: "r"(d), "l"(a), "l"(b), "r"(IDESC), "r"(en), "r"(0u) : "memory");
}
__device__ __forceinline__ void mbar_init(uint32_t a, uint32_t cnt) {
    asm volatile("mbarrier.init.shared.b64 [%0], %1;" :: "r"(a), "r"(cnt) : "memory");
}
__device__ __forceinline__ void mbar_arrive(uint32_t a) {
    asm volatile("mbarrier.arrive.shared.b64 _, [%0];" :: "r"(a) : "memory");
}
__device__ __forceinline__ void mbar_expect_tx(uint32_t a, uint32_t bytes) {
    asm volatile("mbarrier.arrive.expect_tx.shared.b64 _, [%0], %1;" :: "r"(a), "r"(bytes) : "memory");
}
__device__ __forceinline__ void mbar_wait(uint32_t a, uint32_t parity) {
    uint32_t done = 0;
    while (!done) {
        asm volatile(
            "{\n\t.reg .pred p;\n\t"
            "mbarrier.try_wait.parity.shared::cta.b64 p, [%1], %2;\n\t"
            "selp.b32 %0, 1, 0, p;\n\t}"
            : "=r"(done) : "r"(a), "r"(parity) : "memory");
    }
}
__device__ __forceinline__ void tc_commit(uint32_t mbar) {
    asm volatile(
        "tcgen05.commit.cta_group::1.mbarrier::arrive::one.shared::cluster.b64 [%0];"
        :: "r"(mbar) : "memory");
}
__device__ __forceinline__ void bulk_copy(uint32_t dst, const void* src, uint32_t bytes, uint32_t mbar) {
    asm volatile(
        "cp.async.bulk.shared::cta.global.mbarrier::complete_tx::bytes [%0], [%1], %2, [%3];"
        :: "r"(dst), "l"(src), "r"(bytes), "r"(mbar) : "memory");
}
#define TC_ALLOC(smem_addr, n) \
    asm volatile("tcgen05.alloc.cta_group::1.sync.aligned.shared::cta.b32 [%0], %1;" \
                 :: "r"(smem_addr), "r"((uint32_t)(n)) : "memory")
#define TC_DEALLOC(tmem, n) \
    asm volatile("tcgen05.dealloc.cta_group::1.sync.aligned.b32 %0, %1;" :: "r"(tmem), "r"((uint32_t)(n)))
#define TC_RELINQ() \
    asm volatile("tcgen05.relinquish_alloc_permit.cta_group::1.sync.aligned;")
#define TC_FENCE_AFTER()  asm volatile("tcgen05.fence::after_thread_sync;" ::: "memory")
#define TC_FENCE_BEFORE() asm volatile("tcgen05.fence::before_thread_sync;" ::: "memory")
#define TC_WAIT_LD()      asm volatile("tcgen05.wait::ld.sync.aligned;" ::: "memory")
#define FENCE_ASYNC()     asm volatile("fence.proxy.async.shared::cta;" ::: "memory")

#define LDTM_X32(r, addr) \
    asm volatile( \
        "tcgen05.ld.sync.aligned.32x32b.x32.b32 " \
        "{%0, %1, %2, %3, %4, %5, %6, %7, " \
        " %8, %9, %10, %11, %12, %13, %14, %15, " \
        " %16, %17, %18, %19, %20, %21, %22, %23, " \
        " %24, %25, %26, %27, %28, %29, %30, %31}, [%32];" \
        : "=r"((r)[0]),  "=r"((r)[1]),  "=r"((r)[2]),  "=r"((r)[3]), \
          "=r"((r)[4]),  "=r"((r)[5]),  "=r"((r)[6]),  "=r"((r)[7]), \
          "=r"((r)[8]),  "=r"((r)[9]),  "=r"((r)[10]), "=r"((r)[11]), \
          "=r"((r)[12]), "=r"((r)[13]), "=r"((r)[14]), "=r"((r)[15]), \
          "=r"((r)[16]), "=r"((r)[17]), "=r"((r)[18]), "=r"((r)[19]), \
          "=r"((r)[20]), "=r"((r)[21]), "=r"((r)[22]), "=r"((r)[23]), \
          "=r"((r)[24]), "=r"((r)[25]), "=r"((r)[26]), "=r"((r)[27]), \
          "=r"((r)[28]), "=r"((r)[29]), "=r"((r)[30]), "=r"((r)[31]) \
        : "r"(addr))
#endif  // VQ_TC

#define PROD_BAR() asm volatile("bar.sync 1, 256;" ::: "memory")

// ---------------- Main kernel ----------------
extern __shared__ char smem[];

__global__ __launch_bounds__(NTHREADS, 2)
void vq_mma_kernel(const float* __restrict__ x, const float* __restrict__ cb,
                   float* __restrict__ out) {
#if VQ_TC
    const uint32_t sb = smem_u32(smem);
    const int tid = threadIdx.x;
    const int wid = tid >> 5;
    const int lid = tid & 31;
    const int tile = blockIdx.x;
    const int m0 = tile * MT;

    if (wid == 8) {
        TC_ALLOC(sb + SM_TMEMPTR, 256);   // 2 banks of 128 cols
        TC_RELINQ();
    }
    if (tid == 0) {
#pragma unroll
        for (int s = 0; s < NSLOTS; s++) {
            mbar_init(sb + MB_FULL(s), 1);
            mbar_init(sb + MB_EMPTY(s), 1);
        }
        mbar_init(sb + MB_EPI(0), 1);
        mbar_init(sb + MB_EPI(1), 1);
        mbar_init(sb + MB_EPIDONE(0), 256);
        mbar_init(sb + MB_EPIDONE(1), 256);
        FENCE_ASYNC();
    }
    float* c2s = (float*)(smem + SM_C2);
    if (tid < 256)
        for (int i = tid; i < K_CODES; i += 256) c2s[i] = g_c2[i];
    __syncthreads();

    uint32_t tmem;
    asm volatile("ld.shared.b32 %0, [%1];" : "=r"(tmem) : "r"(sb + SM_TMEMPTR));

    if (tid < 256) {
        // ================= epilogue warps =================
        // bank N=128: warpgroup 0 -> cols [0,64), wg1 -> cols [64,128)
        const int grp = wid >> 2;
        float bd[8];
        int   bi[8];
#pragma unroll
        for (int s8 = 0; s8 < 8; s8++) { bd[s8] = 3.4e38f; bi[s8] = 0; }

        for (int pc = 0; pc < NCHUNKS; pc++) {
            const int bank = pc & 1;
            const int u = pc >> 1;
            mbar_wait(sb + MB_EPI(bank), u & 1);
            TC_FENCE_AFTER();
            const uint32_t accoff = (uint32_t)bank * 128 + (uint32_t)grp * 64;
            const int n0p = pc * NCH;
#pragma unroll
            for (int cbk = 0; cbk < 2; cbk++) {
                uint32_t r[32];
                LDTM_X32(r, tmem + accoff + cbk * 32);
                TC_WAIT_LD();
                const int cb0 = n0p + grp * 64 + cbk * 32;
#pragma unroll
                for (int c = 0; c < 32; c++) {
                    float d2 = fmaf(-2.f, __uint_as_float(r[c]), c2s[cb0 + c]);
                    const int s8 = c & 7;
                    if (d2 < bd[s8]) { bd[s8] = d2; bi[s8] = cb0 + c; }
                }
            }
            TC_FENCE_BEFORE();
            mbar_arrive(sb + MB_EPIDONE(bank));
        }
        // merge 8 slots (lowest index wins exact ties -> order-independent)
        float bestd = bd[0];
        int besti = bi[0];
#pragma unroll
        for (int s8 = 1; s8 < 8; s8++) {
            if (bd[s8] < bestd || (bd[s8] == bestd && bi[s8] < besti)) {
                bestd = bd[s8]; besti = bi[s8];
            }
        }

        // ---- merge warpgroup candidates, gather output ----
        {
            int t = (wid & 3) * 32 + lid;
            ((float*)(smem + SM_REDD))[grp * 128 + t] = bestd;
            ((int*)(smem + SM_REDI))[grp * 128 + t] = besti;
        }
        PROD_BAR();
        if (tid < MT) {
            float d0v = ((float*)(smem + SM_REDD))[tid];
            float d1v = ((float*)(smem + SM_REDD))[128 + tid];
            int i0 = ((int*)(smem + SM_REDI))[tid];
            int i1 = ((int*)(smem + SM_REDI))[128 + tid];
            int pick = (d1v < d0v || (d1v == d0v && i1 < i0)) ? i1 : i0;
            ((int*)(smem + SM_ASSIGN))[tid] = pick;
        }
        PROD_BAR();
#pragma unroll 8
        for (int t = 0; t < 32; t++) {
            int idx = tid + t * 256;
            int row = idx >> 6, dv = idx & 63;
            int code = ((int*)(smem + SM_ASSIGN))[row];
            float4 v = *(const float4*)(cb + (size_t)code * D_DIM + dv * 4);
            *(float4*)(out + (size_t)(m0 + row) * D_DIM + dv * 4) = v;
        }
    } else if (tid == 256) {
        // ================= loader thread (warp 8 lane 0) =================
        for (int it = 0; it < NSTAGES_TOTAL; it++) {
            const int s = it % NSLOTS;
            const int u = it / NSLOTS;
            const int nc = it >> 3;          // chunk (8 stages per chunk)
            const int kc = it & 7;           // d-slice
            if (it >= NSLOTS) mbar_wait(sb + MB_EMPTY(s), (u + 1) & 1);
            const uint32_t stg = sb + SM_TILES + (uint32_t)s * STAGE_BYTES;
            const uint32_t fmb = sb + MB_FULL(s);
            mbar_expect_tx(fmb, STAGE_BYTES);
            bulk_copy(stg + AS_HI, g_apre[tile][kc], 16384, fmb);
            bulk_copy(stg + BS_HI, g_bpre[nc][kc], 16384, fmb);
        }
    } else if (tid == 288) {
        // ================= MMA thread (warp 9 lane 0) =================
        int it = 0;
        for (int pc = 0; pc < NCHUNKS; pc++) {
            const int bank = pc & 1;
            const int u = pc >> 1;
            if (pc >= 2) mbar_wait(sb + MB_EPIDONE(bank), (u - 1) & 1);  // bank reuse
            const uint32_t dst = tmem + (uint32_t)bank * 128;
            for (int kc = 0; kc < KSTAGES; kc++, it++) {
                const int s = it % NSLOTS;
                const int su = it / NSLOTS;
                mbar_wait(sb + MB_FULL(s), su & 1);
                const uint32_t sbase = sb + SM_TILES + (uint32_t)s * STAGE_BYTES;
                uint64_t ah = make_desc_sw64(sbase + AS_HI);
                uint64_t al = make_desc_sw64(sbase + AS_LO);
                uint64_t bh = make_desc_sw64(sbase + BS_HI);
                uint64_t bl = make_desc_sw64(sbase + BS_LO);
                uint64_t pa[3] = { ah, ah, al };
                uint64_t pb[3] = { bh, bl, bh };
#pragma unroll
                for (int p = 0; p < 3; p++)
#pragma unroll
                    for (int ks = 0; ks < 2; ks++) {  // K=32 -> 2 fp16 k-steps of 16
                        uint32_t en = (kc == 0 && p == 0 && ks == 0) ? 0u : 1u;
                        mma_f16(dst, pa[p] + ks * 2, pb[p] + ks * 2, en);
                    }
                tc_commit(sb + MB_EMPTY(s));
            }
            tc_commit(sb + MB_EPI(bank));   // chunk accumulation complete
        }
        // last uses (u=3) of both banks must drain before dealloc
        mbar_wait(sb + MB_EPIDONE(0), 1);
        mbar_wait(sb + MB_EPIDONE(1), 1);
    }

    __syncthreads();
    if (wid == 8) TC_DEALLOC(tmem, 256);

#else
    // ================= SIMT fallback (plain sm_103 pass) =================
    const int AS_STRIDE = 260, BS_STRIDE = 33, RED_STRIDE = 17;
    float* fs   = (float*)smem;
    float* As   = fs;
    float* Bs   = As + 64 * AS_STRIDE;
    float* redD = Bs + 64 * BS_STRIDE;
    int*   redI = (int*)(redD + 64 * RED_STRIDE);
    int*   assign = redI + 64 * RED_STRIDE;

    const int tid = threadIdx.x;
    if (tid >= 256) return;
    const int tx = tid & 15;
    const int ty = tid >> 4;

    for (int half = 0; half < 2; half++) {
        const int m0 = blockIdx.x * MT + half * 64;
        PROD_BAR();

        for (int idx = tid; idx < 64 * (D_DIM / 4); idx += 256) {
            int row = idx >> 6, dv = idx & 63;
            float4 v = *(const float4*)(x + (size_t)(m0 + row) * D_DIM + dv * 4);
            *(float4*)(As + row * AS_STRIDE + dv * 4) = v;
        }

        float bestd[4];
        int   besti[4];
#pragma unroll
        for (int i = 0; i < 4; i++) { bestd[i] = 3.4e38f; besti[i] = 0; }

        PROD_BAR();

        for (int ncb = 0; ncb < K_CODES / 64; ncb++) {
            const int n0 = ncb * 64;
            float acc[4][4];
#pragma unroll
            for (int i = 0; i < 4; i++)
#pragma unroll
                for (int j = 0; j < 4; j++) acc[i][j] = 0.f;

            for (int dc = 0; dc < D_DIM / 32; dc++) {
                PROD_BAR();
                for (int idx = tid; idx < 64 * 8; idx += 256) {
                    int code = idx >> 3, dv = idx & 7;
                    float4 v = *(const float4*)(cb + (size_t)(n0 + code) * D_DIM + dc * 32 + dv * 4);
                    float* dst = Bs + code * BS_STRIDE + dv * 4;
                    dst[0] = v.x; dst[1] = v.y; dst[2] = v.z; dst[3] = v.w;
                }
                PROD_BAR();
#pragma unroll 8
                for (int kk = 0; kk < 32; kk++) {
                    float a[4], b[4];
#pragma unroll
                    for (int i = 0; i < 4; i++)
                        a[i] = As[(ty * 4 + i) * AS_STRIDE + dc * 32 + kk];
#pragma unroll
                    for (int j = 0; j < 4; j++)
                        b[j] = Bs[(tx + 16 * j) * BS_STRIDE + kk];
#pragma unroll
                    for (int i = 0; i < 4; i++)
#pragma unroll
                        for (int j = 0; j < 4; j++)
                            acc[i][j] += a[i] * b[j];
                }
            }
#pragma unroll
            for (int j = 0; j < 4; j++) {
                int code = n0 + tx + 16 * j;
                float c2v = __ldg(&g_c2[code]);
#pragma unroll
                for (int i = 0; i < 4; i++) {
                    float d2 = c2v - 2.f * acc[i][j];
                    if (d2 < bestd[i] || (d2 == bestd[i] && code < besti[i])) {
                        bestd[i] = d2; besti[i] = code;
                    }
                }
            }
        }

#pragma unroll
        for (int i = 0; i < 4; i++) {
            int row = ty * 4 + i;
            redD[row * RED_STRIDE + tx] = bestd[i];
            redI[row * RED_STRIDE + tx] = besti[i];
        }
        PROD_BAR();
        if (tid < 64) {
            float bd = redD[tid * RED_STRIDE];
            int   bi = redI[tid * RED_STRIDE];
            for (int e = 1; e < 16; e++) {
                float d = redD[tid * RED_STRIDE + e];
                int  ii = redI[tid * RED_STRIDE + e];
                if (d < bd || (d == bd && ii < bi)) { bd = d; bi = ii; }
            }
            assign[tid] = bi;
        }
        PROD_BAR();
        for (int idx = tid; idx < 64 * (D_DIM / 4); idx += 256) {
            int row = idx >> 6, dv = idx & 63;
            float4 v = *(const float4*)(cb + (size_t)assign[row] * D_DIM + dv * 4);
            *(float4*)(out + (size_t)(m0 + row) * D_DIM + dv * 4) = v;
        }
    }
#endif
}

extern "C" void kernel_launch(void* const* d_in, const int* in_sizes, int n_in,
                              void* d_out, int out_size) {
    const float* x  = (const float*)d_in[0];   // [65536, 256]
    const float* cb = (const float*)d_in[1];   // [1024, 256]
    float* out = (float*)d_out;

    int M = in_sizes[0] / D_DIM;

    pre_kernel<<<PRE_BLOCKS, 256>>>(x, cb);

    cudaFuncSetAttribute(vq_mma_kernel, cudaFuncAttributeMaxDynamicSharedMemorySize, SMEM_TOTAL);
    vq_mma_kernel<<<M / MT, NTHREADS, SMEM_TOTAL>>>(x, cb, out);
}

// round 17
// speedup vs baseline: 1.0724x; 1.0724x over previous
#include <cuda_runtime.h>
#include <cuda_fp16.h>
#include <cstdint>

// VectorQuantizer: out[m,:] = codebook[argmin_k (||c_k||^2 - 2 x_m . c_k)]
// M=65536 tokens, D=256, K=1024 codes, fp32.
//
// R17: R14 main kernel (fp16 3-term split, NCH=256, depth 2, occ 2 — best
// measured main at 81.5us) with the A operand split done INLINE by the 256
// epilogue/producer threads (4 float4/thread/stage, register-prefetched), so
// the 29.5us A pre-pass gmem round-trip disappears. B (2MB) stays TMA-fed
// from a tiny pre-split. FULL mbar = 2 arrivals (B tx + producer group).
// Fallback path (plain sm_103 PTX pass): proven SIMT tiled kernel.

#if defined(__CUDA_ARCH_FEAT_SM103_ALL) || defined(__CUDA_ARCH_FEAT_SM100_ALL) || \
    defined(__CUDA_ARCH_SPECIFIC__) || defined(__CUDA_ARCH_FAMILY_SPECIFIC__)
#define VQ_TC 1
#else
#define VQ_TC 0
#endif

#define D_DIM 256
#define K_CODES 1024
#define MT 128                      // tokens per CTA tile (MMA M)
#define NCH 256                     // codes per chunk (MMA N)
#define KC 32                       // d-slice per stage (32 fp16 = 64B rows)
#define NCHUNKS (K_CODES / NCH)     // 4
#define KSTAGES (D_DIM / KC)        // 8 stages per chunk
#define NSTAGES_TOTAL (NCHUNKS * KSTAGES)  // 32
#define NTILES 512                  // 65536 / MT
#define NTHREADS 320                // 8 producer/epilogue warps + B loader + MMA

// ---- SMEM layout (bytes from dynamic smem base) ----
#define SM_TMEMPTR 0
#define MB_FULL0    8
#define MB_FULL1    16
#define MB_EMPTY0   24
#define MB_EMPTY1   32
#define MB_EPI      40
#define MB_EPIDONE  48
#define SM_ASSIGN  128               // 128 * 4B
#define SM_REDD    1024              // [2][128] float
#define SM_REDI    2048              // [2][128] int
#define SM_C2      4096              // 1024 * 4B
#define SM_TILES   8192
// stage layout (SW64, 64B rows of 32 fp16): A hi 8K | A lo 8K | B hi 16K | B lo 16K
#define AS_HI 0
#define AS_LO 8192
#define BS_HI 16384
#define BS_LO 32768
#define STAGE_BYTES 49152
#define SMEM_TOTAL (SM_TILES + 2 * STAGE_BYTES)   // 106496 bytes -> 2 CTAs/SM

// idesc: c=F32(1<<4), a=FP16(0<<7), b=FP16(0<<10), N=256(32<<17), M=128(8<<24)
#define IDESC 0x8400010u

__device__ float g_c2[K_CODES];
// Pre-split fp16 B tiles in SW64-swizzled SMEM byte layout (64B rows).
__device__ __align__(16) uint8_t g_bpre[NCHUNKS][KSTAGES][32768];  // hi 16K | lo 16K

__device__ __forceinline__ uint32_t sw64(uint32_t off) { return off ^ ((off >> 3) & 0x30); }

// split a float4 into packed fp16 hi (uint2) and lo (uint2)
__device__ __forceinline__ void split4(float4 v, uint2& H, uint2& L) {
    __half hx = __float2half_rn(v.x), hy = __float2half_rn(v.y);
    __half hz = __float2half_rn(v.z), hw = __float2half_rn(v.w);
    __half lx = __float2half_rn(v.x - __half2float(hx));
    __half ly = __float2half_rn(v.y - __half2float(hy));
    __half lz = __float2half_rn(v.z - __half2float(hz));
    __half lw = __float2half_rn(v.w - __half2float(hw));
    H.x = (uint32_t)__half_as_ushort(hx) | ((uint32_t)__half_as_ushort(hy) << 16);
    H.y = (uint32_t)__half_as_ushort(hz) | ((uint32_t)__half_as_ushort(hw) << 16);
    L.x = (uint32_t)__half_as_ushort(lx) | ((uint32_t)__half_as_ushort(ly) << 16);
    L.y = (uint32_t)__half_as_ushort(lz) | ((uint32_t)__half_as_ushort(lw) << 16);
}

// Fused pre-pass: blocks [0,32) B split; [32,36) c2. Tiny (~2MB traffic).
#define BPRE_BLOCKS (NCHUNKS * KSTAGES)         // 32
#define PRE_BLOCKS (BPRE_BLOCKS + 4)

__global__ void pre_kernel(const float* __restrict__ cb) {
    const int bid = blockIdx.x;
    const int tid = threadIdx.x;
    if (bid < BPRE_BLOCKS) {
        const int chunk = bid >> 3;
        const int kc = bid & 7;
        const int n0 = chunk * NCH;
        uint8_t* dst = g_bpre[chunk][kc];
#pragma unroll
        for (int t = 0; t < 8; t++) {
            int idx = tid + t * 256;            // 2048 float4 (256 rows x 8 f4/row)
            int row = idx >> 3, dv = idx & 7;
            float4 v = *(const float4*)(cb + (size_t)(n0 + row) * D_DIM + kc * KC + dv * 4);
            uint2 H, L;
            split4(v, H, L);
            uint32_t off = sw64((uint32_t)row * 64 + dv * 8);
            *(uint2*)(dst + off) = H;
            *(uint2*)(dst + 16384 + off) = L;
        }
    } else {
        const int k = (bid - BPRE_BLOCKS) * 256 + tid;
        if (k < K_CODES) {
            const float4* p = (const float4*)(cb + (size_t)k * D_DIM);
            float s = 0.f;
#pragma unroll 8
            for (int i = 0; i < D_DIM / 4; i++) {
                float4 v = p[i];
                s += v.x * v.x + v.y * v.y + v.z * v.z + v.w * v.w;
            }
            g_c2[k] = s;
        }
    }
}

// ---------------- helpers ----------------
__device__ __forceinline__ uint32_t smem_u32(const void* p) {
    uint32_t a;
    asm("{ .reg .u64 t; cvta.to.shared.u64 t, %1; cvt.u32.u64 %0, t; }" : "=r"(a) : "l"(p));
    return a;
}

#if VQ_TC
__device__ __forceinline__ uint64_t make_desc_sw64(uint32_t addr) {
    // SW64 K-major: layout=4, version=1, SBO=32 (512B = 8 rows x 64B), LBO=1
    uint64_t d = ((uint64_t)4 << 61) | ((uint64_t)1 << 46) | ((uint64_t)32 << 32) | ((uint64_t)1 << 16);
    return d | (uint64_t)((addr >> 4) & 0x3FFF);
}
__device__ __forceinline__ void mma_f16(uint32_t d, uint64_t a, uint64_t b, uint32_t en) {
    asm volatile(
        "{\n\t.reg .pred p;\n\tsetp.ne.u32 p, %4, 0;\n\t"
        "tcgen05.mma.cta_group::1.kind::f16 [%0], %1, %2, %3, {%5, %5, %5, %5}, p;\n\t}"
        :: "r"(d), "l"(a), "l"(b), "r"(IDESC), "r"(en), "r"(0u) : "memory");
}
__device__ __forceinline__ void mbar_init(uint32_t a, uint32_t cnt) {
    asm volatile("mbarrier.init.shared.b64 [%0], %1;" :: "r"(a), "r"(cnt) : "memory");
}
__device__ __forceinline__ void mbar_arrive(uint32_t a) {
    asm volatile("mbarrier.arrive.shared.b64 _, [%0];" :: "r"(a) : "memory");
}
__device__ __forceinline__ void mbar_expect_tx(uint32_t a, uint32_t bytes) {
    asm volatile("mbarrier.arrive.expect_tx.shared.b64 _, [%0], %1;" :: "r"(a), "r"(bytes) : "memory");
}
__device__ __forceinline__ void mbar_wait(uint32_t a, uint32_t parity) {
    uint32_t done = 0;
    while (!done) {
        asm volatile(
            "{\n\t.reg .pred p;\n\t"
            "mbarrier.try_wait.parity.shared::cta.b64 p, [%1], %2;\n\t"
            "selp.b32 %0, 1, 0, p;\n\t}"
            : "=r"(done) : "r"(a), "r"(parity) : "memory");
    }
}
__device__ __forceinline__ void tc_commit(uint32_t mbar) {
    asm volatile(
        "tcgen05.commit.cta_group::1.mbarrier::arrive::one.shared::cluster.b64 [%0];"
        :: "r"(mbar) : "memory");
}
__device__ __forceinline__ void bulk_copy(uint32_t dst, const void* src, uint32_t bytes, uint32_t mbar) {
    asm volatile(
        "cp.async.bulk.shared::cta.global.mbarrier::complete_tx::bytes [%0], [%1], %2, [%3];"
        :: "r"(dst), "l"(src), "r"(bytes), "r"(mbar) : "memory");
}
#define TC_ALLOC(smem_addr, n) \
    asm volatile("tcgen05.alloc.cta_group::1.sync.aligned.shared::cta.b32 [%0], %1;" \
                 :: "r"(smem_addr), "r"((uint32_t)(n)) : "memory")
#define TC_DEALLOC(tmem, n) \
    asm volatile("tcgen05.dealloc.cta_group::1.sync.aligned.b32 %0, %1;" :: "r"(tmem), "r"((uint32_t)(n)))
#define TC_RELINQ() \
    asm volatile("tcgen05.relinquish_alloc_permit.cta_group::1.sync.aligned;")
#define TC_FENCE_AFTER()  asm volatile("tcgen05.fence::after_thread_sync;" ::: "memory")
#define TC_FENCE_BEFORE() asm volatile("tcgen05.fence::before_thread_sync;" ::: "memory")
#define TC_WAIT_LD()      asm volatile("tcgen05.wait::ld.sync.aligned;" ::: "memory")
#define FENCE_ASYNC()     asm volatile("fence.proxy.async.shared::cta;" ::: "memory")

#define LDTM_X32(r, addr) \
    asm volatile( \
        "tcgen05.ld.sync.aligned.32x32b.x32.b32 " \
        "{%0, %1, %2, %3, %4, %5, %6, %7, " \
        " %8, %9, %10, %11, %12, %13, %14, %15, " \
        " %16, %17, %18, %19, %20, %21, %22, %23, " \
        " %24, %25, %26, %27, %28, %29, %30, %31}, [%32];" \
        : "=r"((r)[0]),  "=r"((r)[1]),  "=r"((r)[2]),  "=r"((r)[3]), \
          "=r"((r)[4]),  "=r"((r)[5]),  "=r"((r)[6]),  "=r"((r)[7]), \
          "=r"((r)[8]),  "=r"((r)[9]),  "=r"((r)[10]), "=r"((r)[11]), \
          "=r"((r)[12]), "=r"((r)[13]), "=r"((r)[14]), "=r"((r)[15]), \
          "=r"((r)[16]), "=r"((r)[17]), "=r"((r)[18]), "=r"((r)[19]), \
          "=r"((r)[20]), "=r"((r)[21]), "=r"((r)[22]), "=r"((r)[23]), \
          "=r"((r)[24]), "=r"((r)[25]), "=r"((r)[26]), "=r"((r)[27]), \
          "=r"((r)[28]), "=r"((r)[29]), "=r"((r)[30]), "=r"((r)[31]) \
        : "r"(addr))
#endif  // VQ_TC

#define PROD_BAR() asm volatile("bar.sync 1, 256;" ::: "memory")

// ---------------- Main kernel ----------------
extern __shared__ char smem[];

__global__ __launch_bounds__(NTHREADS, 2)
void vq_mma_kernel(const float* __restrict__ x, const float* __restrict__ cb,
                   float* __restrict__ out) {
#if VQ_TC
    const uint32_t sb = smem_u32(smem);
    const int tid = threadIdx.x;
    const int wid = tid >> 5;
    const int lid = tid & 31;
    const int tile = blockIdx.x;
    const int m0 = tile * MT;

    if (wid == 8) {
        TC_ALLOC(sb + SM_TMEMPTR, 256);
        TC_RELINQ();
    }
    if (tid == 0) {
        mbar_init(sb + MB_FULL0, 2);   // B expect_tx arrive + producer-group arrive
        mbar_init(sb + MB_FULL1, 2);
        mbar_init(sb + MB_EMPTY0, 1);
        mbar_init(sb + MB_EMPTY1, 1);
        mbar_init(sb + MB_EPI, 1);
        mbar_init(sb + MB_EPIDONE, 256);
        FENCE_ASYNC();
    }
    float* c2s = (float*)(smem + SM_C2);
    if (tid < 256)
        for (int i = tid; i < K_CODES; i += 256) c2s[i] = g_c2[i];
    __syncthreads();

    uint32_t tmem;
    asm volatile("ld.shared.b32 %0, [%1];" : "=r"(tmem) : "r"(sb + SM_TMEMPTR));

    if (tid < 256) {
        // ======== producer + epilogue warps (0-7) ========
        const int grp = wid >> 2;      // 0 -> cols [0,128), 1 -> [128,256)
        float bd[8];
        int   bi[8];
#pragma unroll
        for (int s8 = 0; s8 < 8; s8++) { bd[s8] = 3.4e38f; bi[s8] = 0; }

        int eph0 = 0, eph1 = 0;
        // register prefetch of stage 0's A slice (4 float4/thread)
        const int arow = tid >> 3, adv = tid & 7;   // base mapping reused each stage
        float4 va[4];
#pragma unroll
        for (int t = 0; t < 4; t++) {
            int idx = tid + t * 256;
            int row = idx >> 3, dv = idx & 7;
            va[t] = *(const float4*)(x + (size_t)(m0 + row) * D_DIM + dv * 4);
        }
        (void)arow; (void)adv;

        int it = 0;
        for (int nc = 0; nc < NCHUNKS; nc++) {
            for (int kc = 0; kc < KSTAGES; kc++, it++) {
                const int s = it & 1;
                if (it >= 2) {
                    if (s == 0) { mbar_wait(sb + MB_EMPTY0, eph0); eph0 ^= 1; }
                    else        { mbar_wait(sb + MB_EMPTY1, eph1); eph1 ^= 1; }
                }
                char* stg = smem + SM_TILES + s * STAGE_BYTES;
#pragma unroll
                for (int t = 0; t < 4; t++) {
                    int idx = tid + t * 256;
                    int row = idx >> 3, dv = idx & 7;
                    uint2 H, L;
                    split4(va[t], H, L);
                    uint32_t off = sw64((uint32_t)row * 64 + dv * 8);
                    *(uint2*)(stg + AS_HI + off) = H;
                    *(uint2*)(stg + AS_LO + off) = L;
                }
                PROD_BAR();
                if (tid == 0) {
                    FENCE_ASYNC();
                    mbar_arrive(sb + (s ? MB_FULL1 : MB_FULL0));
                }
                if (it + 1 < NSTAGES_TOTAL) {     // prefetch next stage's A slice
                    const int kcn = (it + 1) & 7;
#pragma unroll
                    for (int t = 0; t < 4; t++) {
                        int idx = tid + t * 256;
                        int row = idx >> 3, dv = idx & 7;
                        va[t] = *(const float4*)(x + (size_t)(m0 + row) * D_DIM + kcn * KC + dv * 4);
                    }
                }
            }
            // -------- epilogue for chunk nc --------
            mbar_wait(sb + MB_EPI, nc & 1);
            TC_FENCE_AFTER();
            const uint32_t accoff = (uint32_t)grp * 128;
            const int n0p = nc * NCH;
#pragma unroll
            for (int cbk = 0; cbk < 4; cbk++) {
                uint32_t r[32];
                LDTM_X32(r, tmem + accoff + cbk * 32);
                TC_WAIT_LD();
                const int cb0 = n0p + grp * 128 + cbk * 32;
#pragma unroll
                for (int c = 0; c < 32; c++) {
                    float d2 = fmaf(-2.f, __uint_as_float(r[c]), c2s[cb0 + c]);
                    const int s8 = c & 7;
                    if (d2 < bd[s8]) { bd[s8] = d2; bi[s8] = cb0 + c; }
                }
            }
            TC_FENCE_BEFORE();
            mbar_arrive(sb + MB_EPIDONE);
        }
        // merge 8 slots (lowest index wins exact ties -> order-independent)
        float bestd = bd[0];
        int besti = bi[0];
#pragma unroll
        for (int s8 = 1; s8 < 8; s8++) {
            if (bd[s8] < bestd || (bd[s8] == bestd && bi[s8] < besti)) {
                bestd = bd[s8]; besti = bi[s8];
            }
        }

        // ---- merge warpgroup candidates, gather output ----
        {
            int t = (wid & 3) * 32 + lid;
            ((float*)(smem + SM_REDD))[grp * 128 + t] = bestd;
            ((int*)(smem + SM_REDI))[grp * 128 + t] = besti;
        }
        PROD_BAR();
        if (tid < MT) {
            float d0v = ((float*)(smem + SM_REDD))[tid];
            float d1v = ((float*)(smem + SM_REDD))[128 + tid];
            int i0 = ((int*)(smem + SM_REDI))[tid];
            int i1 = ((int*)(smem + SM_REDI))[128 + tid];
            int pick = (d1v < d0v || (d1v == d0v && i1 < i0)) ? i1 : i0;
            ((int*)(smem + SM_ASSIGN))[tid] = pick;
        }
        PROD_BAR();
#pragma unroll 8
        for (int t = 0; t < 32; t++) {
            int idx = tid + t * 256;
            int row = idx >> 6, dv = idx & 63;
            int code = ((int*)(smem + SM_ASSIGN))[row];
            float4 v = *(const float4*)(cb + (size_t)code * D_DIM + dv * 4);
            *(float4*)(out + (size_t)(m0 + row) * D_DIM + dv * 4) = v;
        }
    } else if (tid == 256) {
        // ================= B loader thread (warp 8 lane 0) =================
        int eph0 = 0, eph1 = 0;
        for (int it = 0; it < NSTAGES_TOTAL; it++) {
            const int s = it & 1;
            const int nc = it >> 3;          // chunk (8 stages per chunk)
            const int kc = it & 7;           // d-slice
            if (it >= 2) {
                if (s == 0) { mbar_wait(sb + MB_EMPTY0, eph0); eph0 ^= 1; }
                else        { mbar_wait(sb + MB_EMPTY1, eph1); eph1 ^= 1; }
            }
            const uint32_t stg = sb + SM_TILES + (uint32_t)s * STAGE_BYTES;
            const uint32_t fmb = sb + (s ? MB_FULL1 : MB_FULL0);
            mbar_expect_tx(fmb, 32768);
            bulk_copy(stg + BS_HI, g_bpre[nc][kc], 32768, fmb);
        }
    } else if (tid == 288) {
        // ================= MMA thread (warp 9 lane 0) =================
        int fph0 = 0, fph1 = 0;
        int it = 0;
        for (int nc = 0; nc < NCHUNKS; nc++) {
            if (nc >= 1) mbar_wait(sb + MB_EPIDONE, (nc - 1) & 1);  // accumulator reuse
            for (int kc = 0; kc < KSTAGES; kc++, it++) {
                const int s = it & 1;
                if (s == 0) { mbar_wait(sb + MB_FULL0, fph0); fph0 ^= 1; }
                else        { mbar_wait(sb + MB_FULL1, fph1); fph1 ^= 1; }
                const uint32_t sbase = sb + SM_TILES + (uint32_t)s * STAGE_BYTES;
                uint64_t ah = make_desc_sw64(sbase + AS_HI);
                uint64_t al = make_desc_sw64(sbase + AS_LO);
                uint64_t bh = make_desc_sw64(sbase + BS_HI);
                uint64_t bl = make_desc_sw64(sbase + BS_LO);
                uint64_t pa[3] = { ah, ah, al };
                uint64_t pb[3] = { bh, bl, bh };
#pragma unroll
                for (int p = 0; p < 3; p++)
#pragma unroll
                    for (int ks = 0; ks < 2; ks++) {  // K=32 -> 2 fp16 k-steps of 16
                        uint32_t en = (kc == 0 && p == 0 && ks == 0) ? 0u : 1u;
                        mma_f16(tmem, pa[p] + ks * 2, pb[p] + ks * 2, en);
                    }
                tc_commit(sb + (s ? MB_EMPTY1 : MB_EMPTY0));
            }
            tc_commit(sb + MB_EPI);   // chunk accumulation complete
        }
        mbar_wait(sb + MB_EPIDONE, (NCHUNKS - 1) & 1);  // last epilogue done
    }

    __syncthreads();
    if (wid == 8) TC_DEALLOC(tmem, 256);

#else
    // ================= SIMT fallback (plain sm_103 pass) =================
    const int AS_STRIDE = 260, BS_STRIDE = 33, RED_STRIDE = 17;
    float* fs   = (float*)smem;
    float* As   = fs;
    float* Bs   = As + 64 * AS_STRIDE;
    float* redD = Bs + 64 * BS_STRIDE;
    int*   redI = (int*)(redD + 64 * RED_STRIDE);
    int*   assign = redI + 64 * RED_STRIDE;

    const int tid = threadIdx.x;
    if (tid >= 256) return;
    const int tx = tid & 15;
    const int ty = tid >> 4;

    for (int half = 0; half < 2; half++) {
        const int m0 = blockIdx.x * MT + half * 64;
        PROD_BAR();

        for (int idx = tid; idx < 64 * (D_DIM / 4); idx += 256) {
            int row = idx >> 6, dv = idx & 63;
            float4 v = *(const float4*)(x + (size_t)(m0 + row) * D_DIM + dv * 4);
            *(float4*)(As + row * AS_STRIDE + dv * 4) = v;
        }

        float bestd[4];
        int   besti[4];
#pragma unroll
        for (int i = 0; i < 4; i++) { bestd[i] = 3.4e38f; besti[i] = 0; }

        PROD_BAR();

        for (int ncb = 0; ncb < K_CODES / 64; ncb++) {
            const int n0 = ncb * 64;
            float acc[4][4];
#pragma unroll
            for (int i = 0; i < 4; i++)
#pragma unroll
                for (int j = 0; j < 4; j++) acc[i][j] = 0.f;

            for (int dc = 0; dc < D_DIM / 32; dc++) {
                PROD_BAR();
                for (int idx = tid; idx < 64 * 8; idx += 256) {
                    int code = idx >> 3, dv = idx & 7;
                    float4 v = *(const float4*)(cb + (size_t)(n0 + code) * D_DIM + dc * 32 + dv * 4);
                    float* dst = Bs + code * BS_STRIDE + dv * 4;
                    dst[0] = v.x; dst[1] = v.y; dst[2] = v.z; dst[3] = v.w;
                }
                PROD_BAR();
#pragma unroll 8
                for (int kk = 0; kk < 32; kk++) {
                    float a[4], b[4];
#pragma unroll
                    for (int i = 0; i < 4; i++)
                        a[i] = As[(ty * 4 + i) * AS_STRIDE + dc * 32 + kk];
#pragma unroll
                    for (int j = 0; j < 4; j++)
                        b[j] = Bs[(tx + 16 * j) * BS_STRIDE + kk];
#pragma unroll
                    for (int i = 0; i < 4; i++)
#pragma unroll
                        for (int j = 0; j < 4; j++)
                            acc[i][j] += a[i] * b[j];
                }
            }
#pragma unroll
            for (int j = 0; j < 4; j++) {
                int code = n0 + tx + 16 * j;
                float c2v = __ldg(&g_c2[code]);
#pragma unroll
                for (int i = 0; i < 4; i++) {
                    float d2 = c2v - 2.f * acc[i][j];
                    if (d2 < bestd[i] || (d2 == bestd[i] && code < besti[i])) {
                        bestd[i] = d2; besti[i] = code;
                    }
                }
            }
        }

#pragma unroll
        for (int i = 0; i < 4; i++) {
            int row = ty * 4 + i;
            redD[row * RED_STRIDE + tx] = bestd[i];
            redI[row * RED_STRIDE + tx] = besti[i];
        }
        PROD_BAR();
        if (tid < 64) {
            float bd = redD[tid * RED_STRIDE];
            int   bi = redI[tid * RED_STRIDE];
            for (int e = 1; e < 16; e++) {
                float d = redD[tid * RED_STRIDE + e];
                int  ii = redI[tid * RED_STRIDE + e];
                if (d < bd || (d == bd && ii < bi)) { bd = d; bi = ii; }
            }
            assign[tid] = bi;
        }
        PROD_BAR();
        for (int idx = tid; idx < 64 * (D_DIM / 4); idx += 256) {
            int row = idx >> 6, dv = idx & 63;
            float4 v = *(const float4*)(cb + (size_t)assign[row] * D_DIM + dv * 4);
            *(float4*)(out + (size_t)(m0 + row) * D_DIM + dv * 4) = v;
        }
    }
#endif
}

extern "C" void kernel_launch(void* const* d_in, const int* in_sizes, int n_in,
                              void* d_out, int out_size) {
    const float* x  = (const float*)d_in[0];   // [65536, 256]
    const float* cb = (const float*)d_in[1];   // [1024, 256]
    float* out = (float*)d_out;

    int M = in_sizes[0] / D_DIM;

    pre_kernel<<<PRE_BLOCKS, 256>>>(cb);

    cudaFuncSetAttribute(vq_mma_kernel, cudaFuncAttributeMaxDynamicSharedMemorySize, SMEM_TOTAL);
    vq_mma_kernel<<<M / MT, NTHREADS, SMEM_TOTAL>>>(x, cb, out);
}